// round 1
// baseline (speedup 1.0000x reference)
#include <cuda_runtime.h>
#include <math.h>

// Problem constants
#define NB    16          // n
#define CDIM  512         // c
#define TDIM  256         // t
#define VV    25          // vv
#define HEADS 8
#define HD    64
#define MCOL  6400        // t*vv, columns per batch-n GEMM
#define QROWS 1536        // 3*c

// Scratch (allocation-free rule: __device__ globals)
__device__ float g_qkv[(size_t)NB * QROWS * MCOL];   // 629 MB: [n][1536][6400]
__device__ float g_att[(size_t)NB * CDIM * MCOL];    // 210 MB: [n][512][6400]

// ---------------------------------------------------------------------------
// Classic 128x128x8 SGEMM, 256 threads, 8x8 per thread, global prefetch.
// C[M,N] = A[M,K] @ B[K,N], all row-major. Batched over blockIdx.z via
// strides on B and C (A shared across batches).
// ---------------------------------------------------------------------------
#define BM 128
#define BN 128
#define BK 8
#define TM 8
#define TN 8

__global__ __launch_bounds__(256, 2)
void sgemm_kernel(const float* __restrict__ A,
                  const float* __restrict__ B,
                  float* __restrict__ C,
                  int M, int N, int K, long sB, long sC)
{
    B += (long)blockIdx.z * sB;
    C += (long)blockIdx.z * sC;
    const int bm = blockIdx.y * BM;
    const int bn = blockIdx.x * BN;

    __shared__ float As[BK][BM];
    __shared__ float Bs[BK][BN];

    const int tid  = threadIdx.x;
    const int aRow = tid >> 1;            // 0..127
    const int aCol = (tid & 1) << 2;      // 0 or 4
    const int bRow = tid >> 5;            // 0..7
    const int bCol = (tid & 31) << 2;     // 0..124

    const int ty = tid >> 4;              // 0..15
    const int tx = tid & 15;              // 0..15
    const int rowBase = ty * TM;
    const int colBase = tx * TN;

    const float* Ag = A + (long)(bm + aRow) * K + aCol;
    const float* Bg = B + (long)bRow * N + bn + bCol;

    float acc[TM][TN] = {};
    float ra[TM], rb[TN];

    float4 av = *(const float4*)(Ag);
    float4 bv = *(const float4*)(Bg);

    for (int k0 = 0; k0 < K; k0 += BK) {
        As[aCol + 0][aRow] = av.x;
        As[aCol + 1][aRow] = av.y;
        As[aCol + 2][aRow] = av.z;
        As[aCol + 3][aRow] = av.w;
        *(float4*)&Bs[bRow][bCol] = bv;
        __syncthreads();

        if (k0 + BK < K) {
            av = *(const float4*)(Ag + k0 + BK);
            bv = *(const float4*)(Bg + (long)(k0 + BK) * N);
        }

        #pragma unroll
        for (int k = 0; k < BK; k++) {
            #pragma unroll
            for (int i = 0; i < TM; i++) ra[i] = As[k][rowBase + i];
            #pragma unroll
            for (int j = 0; j < TN; j++) rb[j] = Bs[k][colBase + j];
            #pragma unroll
            for (int i = 0; i < TM; i++)
                #pragma unroll
                for (int j = 0; j < TN; j++)
                    acc[i][j] += ra[i] * rb[j];
        }
        __syncthreads();
    }

    #pragma unroll
    for (int i = 0; i < TM; i++) {
        float* Crow = C + (long)(bm + rowBase + i) * N + bn + colBase;
        *(float4*)(Crow)     = make_float4(acc[i][0], acc[i][1], acc[i][2], acc[i][3]);
        *(float4*)(Crow + 4) = make_float4(acc[i][4], acc[i][5], acc[i][6], acc[i][7]);
    }
}

// ---------------------------------------------------------------------------
// Attention middle: one CTA per (n,t) token-block. All 8 heads in one CTA
// because softmax runs over the HEADS axis. warp h <-> head h, lanes = i
// (query row), so K/V smem reads broadcast across the warp.
// Dynamic smem: qkv tile [1536][25] + attn [8][25][25] = 173,600 B.
// ---------------------------------------------------------------------------
__global__ __launch_bounds__(256, 1)
void attn_kernel(const float* __restrict__ qkv, float* __restrict__ att)
{
    extern __shared__ float smem[];
    float* qs = smem;                    // [1536*25]
    float* as = smem + QROWS * VV;       // [8*625]

    const int b  = blockIdx.x;
    const int n  = b >> 8;               // t = 256
    const int ti = b & 255;
    const float* src = qkv + (long)n * QROWS * MCOL + ti * VV;
    const int tid = threadIdx.x;

    // Stage qkv[:, ti*25 .. ti*25+24] into smem
    for (int idx = tid; idx < QROWS * VV; idx += 256) {
        int row = idx / VV;
        int j   = idx - row * VV;
        qs[idx] = src[(long)row * MCOL + j];
    }
    __syncthreads();

    const int h = tid >> 5;
    const int i = tid & 31;

    // Phase 1: attn[h][i][j] = scale * q_i . k_j   (q in regs, k broadcast)
    if (i < VV) {
        float q[HD];
        #pragma unroll
        for (int d = 0; d < HD; d++) q[d] = qs[(h * HD + d) * VV + i];
        const float* kb = qs + (CDIM + h * HD) * VV;
        for (int j = 0; j < VV; j++) {
            float acc = 0.f;
            #pragma unroll
            for (int d = 0; d < HD; d++) acc += q[d] * kb[d * VV + j];
            as[h * 625 + i * VV + j] = acc * 0.125f;   // hd^-0.5
        }
    }
    __syncthreads();

    // Phase 2: softmax over heads axis for each (i,j)
    for (int p = tid; p < 625; p += 256) {
        float v[HEADS];
        #pragma unroll
        for (int hh = 0; hh < HEADS; hh++) v[hh] = as[hh * 625 + p];
        float m = v[0];
        #pragma unroll
        for (int hh = 1; hh < HEADS; hh++) m = fmaxf(m, v[hh]);
        float s = 0.f;
        #pragma unroll
        for (int hh = 0; hh < HEADS; hh++) { v[hh] = expf(v[hh] - m); s += v[hh]; }
        float inv = 1.f / s;
        #pragma unroll
        for (int hh = 0; hh < HEADS; hh++) as[hh * 625 + p] = v[hh] * inv;
    }
    __syncthreads();

    // Phase 3: out[h][i][d] = sum_j attn[h][i][j] * v[h][j][d], write [ci,m] layout
    if (i < VV) {
        float o[HD];
        #pragma unroll
        for (int d = 0; d < HD; d++) o[d] = 0.f;
        const float* vb = qs + (2 * CDIM + h * HD) * VV;
        const float* ar = as + h * 625 + i * VV;
        for (int j = 0; j < VV; j++) {
            float a = ar[j];
            #pragma unroll
            for (int d = 0; d < HD; d++) o[d] += a * vb[d * VV + j];
        }
        float* dst = att + (long)n * CDIM * MCOL + (long)(h * HD) * MCOL + ti * VV + i;
        #pragma unroll
        for (int d = 0; d < HD; d++) dst[(long)d * MCOL] = o[d];
    }
}

// ---------------------------------------------------------------------------
extern "C" void kernel_launch(void* const* d_in, const int* in_sizes, int n_in,
                              void* d_out, int out_size)
{
    const float* x     = (const float*)d_in[0];   // [16,512,256,25]
    const float* wqkv  = (const float*)d_in[1];   // [1536,512]
    const float* wproj = (const float*)d_in[2];   // [512,512]
    float* out = (float*)d_out;                   // [16,512,256,25]

    float *qkv, *att;
    cudaGetSymbolAddress((void**)&qkv, g_qkv);
    cudaGetSymbolAddress((void**)&att, g_att);

    const int smem_bytes = (QROWS * VV + HEADS * 625) * (int)sizeof(float);
    cudaFuncSetAttribute((const void*)attn_kernel,
                         cudaFuncAttributeMaxDynamicSharedMemorySize, smem_bytes);

    dim3 blk(256);
    // QKV: per-n  [1536,6400] = W_qkv[1536,512] @ X_n[512,6400]
    sgemm_kernel<<<dim3(MCOL / BN, QROWS / BM, NB), blk>>>(
        wqkv, x, qkv, QROWS, MCOL, CDIM,
        (long)CDIM * MCOL, (long)QROWS * MCOL);

    // Attention middle: 4096 CTAs (one per (n,t))
    attn_kernel<<<dim3(NB * TDIM), blk, smem_bytes>>>(qkv, att);

    // Proj: per-n  out_n[512,6400] = W_proj[512,512] @ O_n[512,6400]
    sgemm_kernel<<<dim3(MCOL / BN, CDIM / BM, NB), blk>>>(
        wproj, att, out, CDIM, MCOL, CDIM,
        (long)CDIM * MCOL, (long)CDIM * MCOL);
}

// round 2
// speedup vs baseline: 2.9386x; 2.9386x over previous
#include <cuda_runtime.h>
#include <math.h>

// Problem constants
#define NB    16          // n
#define CDIM  512         // c
#define TDIM  256         // t
#define VV    25          // vv
#define HEADS 8
#define HD    64
#define MCOL  6400        // t*vv
#define QROWS 1536        // 3*c

// Scratch (__device__ globals per allocation-free rule)
__device__ float g_qkv[(size_t)NB * QROWS * MCOL];   // [n][1536][6400]
__device__ float g_att[(size_t)NB * CDIM * MCOL];    // [n][512][6400]

// ---------------------------------------------------------------------------
// tf32 tensor-core GEMM: C[M,N] = A[M,K] @ B[K,N], row-major.
// 128x128x16 CTA tile, 8 warps (2x4) of 64x32, mma.sync.m16n8k8.tf32.
// Batched over blockIdx.z via strides on B and C (A shared).
// ---------------------------------------------------------------------------
#define BM 128
#define BN 128
#define BKT 16
#define SPAD 136   // smem row stride (words): bank = (8k+g) -> conflict-free frags

__device__ __forceinline__ unsigned f2tf32(float f) {
    unsigned u;
    asm("cvt.rna.tf32.f32 %0, %1;" : "=r"(u) : "f"(f));
    return u;
}

__device__ __forceinline__ void mma_tf32(float& c0, float& c1, float& c2, float& c3,
                                         unsigned a0, unsigned a1, unsigned a2, unsigned a3,
                                         unsigned b0, unsigned b1) {
    asm volatile(
        "mma.sync.aligned.m16n8k8.row.col.f32.tf32.tf32.f32 "
        "{%0,%1,%2,%3}, {%4,%5,%6,%7}, {%8,%9}, {%0,%1,%2,%3};"
        : "+f"(c0), "+f"(c1), "+f"(c2), "+f"(c3)
        : "r"(a0), "r"(a1), "r"(a2), "r"(a3), "r"(b0), "r"(b1));
}

__global__ __launch_bounds__(256, 2)
void mma_gemm(const float* __restrict__ A,
              const float* __restrict__ B,
              float* __restrict__ C,
              int M, int N, int K, long sB, long sC)
{
    B += (long)blockIdx.z * sB;
    C += (long)blockIdx.z * sC;
    const int bm = blockIdx.y * BM;
    const int bn = blockIdx.x * BN;

    __shared__ unsigned As[BKT][SPAD];   // [k][m]
    __shared__ unsigned Bs[BKT][SPAD];   // [k][n]

    const int tid  = threadIdx.x;
    const int warp = tid >> 5;
    const int lane = tid & 31;
    const int g    = lane >> 2;   // group row 0..7
    const int tg   = lane & 3;    // thread-in-group 0..3
    const int wm   = (warp >> 2) * 64;   // warp m-base in tile
    const int wn   = (warp & 3) * 32;    // warp n-base in tile

    // A stage: row = tid>>1 (0..127), 8 cols at (tid&1)*8
    const int arow = tid >> 1, acol = (tid & 1) * 8;
    const float* Ag = A + (long)(bm + arow) * K + acol;
    // B stage: row = tid>>4 (0..15), 8 cols at (tid&15)*8
    const int brow = tid >> 4, bcol = (tid & 15) * 8;
    const float* Bg = B + (long)brow * N + bn + bcol;

    float4 av0 = *(const float4*)(Ag);
    float4 av1 = *(const float4*)(Ag + 4);
    float4 bv0 = *(const float4*)(Bg);
    float4 bv1 = *(const float4*)(Bg + 4);

    float acc[4][4][4] = {};   // [mt][nt][c0..c3]

    for (int k0 = 0; k0 < K; k0 += BKT) {
        // Store A transposed [k][m] with tf32 rounding
        As[acol + 0][arow] = f2tf32(av0.x);
        As[acol + 1][arow] = f2tf32(av0.y);
        As[acol + 2][arow] = f2tf32(av0.z);
        As[acol + 3][arow] = f2tf32(av0.w);
        As[acol + 4][arow] = f2tf32(av1.x);
        As[acol + 5][arow] = f2tf32(av1.y);
        As[acol + 6][arow] = f2tf32(av1.z);
        As[acol + 7][arow] = f2tf32(av1.w);
        // Store B [k][n]
        Bs[brow][bcol + 0] = f2tf32(bv0.x);
        Bs[brow][bcol + 1] = f2tf32(bv0.y);
        Bs[brow][bcol + 2] = f2tf32(bv0.z);
        Bs[brow][bcol + 3] = f2tf32(bv0.w);
        Bs[brow][bcol + 4] = f2tf32(bv1.x);
        Bs[brow][bcol + 5] = f2tf32(bv1.y);
        Bs[brow][bcol + 6] = f2tf32(bv1.z);
        Bs[brow][bcol + 7] = f2tf32(bv1.w);
        __syncthreads();

        if (k0 + BKT < K) {
            av0 = *(const float4*)(Ag + k0 + BKT);
            av1 = *(const float4*)(Ag + k0 + BKT + 4);
            bv0 = *(const float4*)(Bg + (long)(k0 + BKT) * N);
            bv1 = *(const float4*)(Bg + (long)(k0 + BKT) * N + 4);
        }

        #pragma unroll
        for (int ks = 0; ks < BKT; ks += 8) {
            unsigned af[4][4], bf[4][2];
            #pragma unroll
            for (int mt = 0; mt < 4; mt++) {
                const int m = wm + mt * 16;
                af[mt][0] = As[ks + tg    ][m + g];
                af[mt][1] = As[ks + tg    ][m + g + 8];
                af[mt][2] = As[ks + tg + 4][m + g];
                af[mt][3] = As[ks + tg + 4][m + g + 8];
            }
            #pragma unroll
            for (int nt = 0; nt < 4; nt++) {
                const int ncol = wn + nt * 8 + g;
                bf[nt][0] = Bs[ks + tg    ][ncol];
                bf[nt][1] = Bs[ks + tg + 4][ncol];
            }
            #pragma unroll
            for (int mt = 0; mt < 4; mt++)
                #pragma unroll
                for (int nt = 0; nt < 4; nt++)
                    mma_tf32(acc[mt][nt][0], acc[mt][nt][1], acc[mt][nt][2], acc[mt][nt][3],
                             af[mt][0], af[mt][1], af[mt][2], af[mt][3],
                             bf[nt][0], bf[nt][1]);
        }
        __syncthreads();
    }

    // Epilogue: c0,c1 -> (row g, cols 2tg,2tg+1); c2,c3 -> row g+8
    #pragma unroll
    for (int mt = 0; mt < 4; mt++) {
        #pragma unroll
        for (int nt = 0; nt < 4; nt++) {
            const long r0 = bm + wm + mt * 16 + g;
            const int  cc = bn + wn + nt * 8 + 2 * tg;
            *(float2*)(C + r0 * N + cc)       = make_float2(acc[mt][nt][0], acc[mt][nt][1]);
            *(float2*)(C + (r0 + 8) * N + cc) = make_float2(acc[mt][nt][2], acc[mt][nt][3]);
        }
    }
}

// ---------------------------------------------------------------------------
// Attention middle: one CTA per (n,t) token-block, softmax over HEADS axis.
// ---------------------------------------------------------------------------
__global__ __launch_bounds__(256, 1)
void attn_kernel(const float* __restrict__ qkv, float* __restrict__ att)
{
    extern __shared__ float smem[];
    float* qs = smem;                    // [1536*25]
    float* as = smem + QROWS * VV;       // [8*625]

    const int b  = blockIdx.x;
    const int n  = b >> 8;
    const int ti = b & 255;
    const float* src = qkv + (long)n * QROWS * MCOL + ti * VV;
    const int tid = threadIdx.x;

    for (int idx = tid; idx < QROWS * VV; idx += 256) {
        int row = idx / VV;
        int j   = idx - row * VV;
        qs[idx] = src[(long)row * MCOL + j];
    }
    __syncthreads();

    const int h = tid >> 5;
    const int i = tid & 31;

    if (i < VV) {
        float q[HD];
        #pragma unroll
        for (int d = 0; d < HD; d++) q[d] = qs[(h * HD + d) * VV + i];
        const float* kb = qs + (CDIM + h * HD) * VV;
        for (int j = 0; j < VV; j++) {
            float acc = 0.f;
            #pragma unroll
            for (int d = 0; d < HD; d++) acc += q[d] * kb[d * VV + j];
            as[h * 625 + i * VV + j] = acc * 0.125f;
        }
    }
    __syncthreads();

    for (int p = tid; p < 625; p += 256) {
        float v[HEADS];
        #pragma unroll
        for (int hh = 0; hh < HEADS; hh++) v[hh] = as[hh * 625 + p];
        float m = v[0];
        #pragma unroll
        for (int hh = 1; hh < HEADS; hh++) m = fmaxf(m, v[hh]);
        float s = 0.f;
        #pragma unroll
        for (int hh = 0; hh < HEADS; hh++) { v[hh] = expf(v[hh] - m); s += v[hh]; }
        float inv = 1.f / s;
        #pragma unroll
        for (int hh = 0; hh < HEADS; hh++) as[hh * 625 + p] = v[hh] * inv;
    }
    __syncthreads();

    if (i < VV) {
        float o[HD];
        #pragma unroll
        for (int d = 0; d < HD; d++) o[d] = 0.f;
        const float* vb = qs + (2 * CDIM + h * HD) * VV;
        const float* ar = as + h * 625 + i * VV;
        for (int j = 0; j < VV; j++) {
            float a = ar[j];
            #pragma unroll
            for (int d = 0; d < HD; d++) o[d] += a * vb[d * VV + j];
        }
        float* dst = att + (long)n * CDIM * MCOL + (long)(h * HD) * MCOL + ti * VV + i;
        #pragma unroll
        for (int d = 0; d < HD; d++) dst[(long)d * MCOL] = o[d];
    }
}

// ---------------------------------------------------------------------------
extern "C" void kernel_launch(void* const* d_in, const int* in_sizes, int n_in,
                              void* d_out, int out_size)
{
    const float* x     = (const float*)d_in[0];   // [16,512,256,25]
    const float* wqkv  = (const float*)d_in[1];   // [1536,512]
    const float* wproj = (const float*)d_in[2];   // [512,512]
    float* out = (float*)d_out;

    float *qkv, *att;
    cudaGetSymbolAddress((void**)&qkv, g_qkv);
    cudaGetSymbolAddress((void**)&att, g_att);

    const int smem_bytes = (QROWS * VV + HEADS * 625) * (int)sizeof(float);
    cudaFuncSetAttribute((const void*)attn_kernel,
                         cudaFuncAttributeMaxDynamicSharedMemorySize, smem_bytes);

    dim3 blk(256);
    // QKV: per-n [1536,6400] = W_qkv[1536,512] @ X_n[512,6400]
    mma_gemm<<<dim3(MCOL / BN, QROWS / BM, NB), blk>>>(
        wqkv, x, qkv, QROWS, MCOL, CDIM,
        (long)CDIM * MCOL, (long)QROWS * MCOL);

    attn_kernel<<<dim3(NB * TDIM), blk, smem_bytes>>>(qkv, att);

    // Proj: per-n [512,6400] = W_proj[512,512] @ O_n[512,6400]
    mma_gemm<<<dim3(MCOL / BN, CDIM / BM, NB), blk>>>(
        wproj, att, out, CDIM, MCOL, CDIM,
        (long)CDIM * MCOL, (long)CDIM * MCOL);
}

// round 8
// speedup vs baseline: 3.0816x; 1.0486x over previous
#include <cuda_runtime.h>
#include <cstdint>
#include <math.h>

// Problem constants
#define NB    16
#define CDIM  512
#define TDIM  256
#define VV    25
#define HEADS 8
#define HD    64
#define MCOL  6400
#define QROWS 1536

// Scratch (__device__ globals per allocation-free rule)
__device__ float g_qkv[(size_t)NB * QROWS * MCOL];   // QKV output (fp32)
__device__ float g_att[(size_t)NB * CDIM * MCOL];    // attn output (tf32-rounded)
__device__ float g_xr [(size_t)NB * CDIM * MCOL];    // x, tf32-rounded
__device__ float g_wq [QROWS * CDIM];                // w_qkv, tf32-rounded
__device__ float g_wp [CDIM * CDIM];                 // w_proj, tf32-rounded

// ---------------------------------------------------------------------------
__device__ __forceinline__ unsigned f2tf32(float f) {
    unsigned u; asm("cvt.rna.tf32.f32 %0, %1;" : "=r"(u) : "f"(f)); return u;
}
__device__ __forceinline__ uint32_t smem_u32(const void* p) {
    uint32_t a;
    asm("{ .reg .u64 t; cvta.to.shared.u64 t, %1; cvt.u32.u64 %0, t; }" : "=r"(a) : "l"(p));
    return a;
}
__device__ __forceinline__ void mma_tf32(float* c, const uint32_t* a, const uint32_t* b) {
    asm volatile(
        "mma.sync.aligned.m16n8k8.row.col.f32.tf32.tf32.f32 "
        "{%0,%1,%2,%3}, {%4,%5,%6,%7}, {%8,%9}, {%0,%1,%2,%3};"
        : "+f"(c[0]), "+f"(c[1]), "+f"(c[2]), "+f"(c[3])
        : "r"(a[0]), "r"(a[1]), "r"(a[2]), "r"(a[3]), "r"(b[0]), "r"(b[1]));
}
#define CP16(dst, src) \
    asm volatile("cp.async.cg.shared.global [%0], [%1], 16;" :: "r"(dst), "l"(src))
#define CP_COMMIT() asm volatile("cp.async.commit_group;" ::: "memory")

// ---------------------------------------------------------------------------
// tf32 tensor-core GEMM: C[M,N] = A[M,512] @ B[512,N]; A,B pre-rounded to tf32
// bit patterns. CTA 128x128, 4 warps of 64x64, K=512 fixed, 4-stage cp.async.
// A smem: [m][64B], chunk-xor swizzle; fragments via ldmatrix.x4.b16.
// B smem: [k][544B padded rows]; fragments via scalar LDS (conflict-free).
// ---------------------------------------------------------------------------
#define KT      16
#define NSTAGE  4
#define A_STB   (128 * 64)               // 8192 per stage
#define B_STB   (16 * 544)               // 8704 per stage
#define B_BASE  (NSTAGE * A_STB)         // 32768
#define SMEM_G  (B_BASE + NSTAGE * B_STB) // 67584

__global__ __launch_bounds__(128, 2)
void tf32_gemm(const float* __restrict__ A, const float* __restrict__ B,
               float* __restrict__ C, int Nld, long sB, long sC)
{
    extern __shared__ char sm[];
    const uint32_t sbase = smem_u32(sm);
    B += (long)blockIdx.z * sB;
    C += (long)blockIdx.z * sC;
    const int bm = blockIdx.y * 128;
    const int bn = blockIdx.x * 128;

    const int tid  = threadIdx.x;
    const int wid  = tid >> 5, lane = tid & 31;
    const int g    = lane >> 2, tg = lane & 3;
    const int wm   = (wid & 1) * 64, wn = (wid >> 1) * 64;

    // ldmatrix per-lane row/chunk selectors
    const int row16 = (lane & 7) + ((lane >> 3) & 1) * 8;  // 0..15
    const int csel  = lane >> 4;                            // 0/1

    // Staging maps
    const float* Ag = A + (long)(bm + tid) * CDIM;          // thread -> one m-row
    const uint32_t a_sw = (uint32_t)((tid >> 1) & 3);
    const int bk = tid >> 3, bc4 = (tid & 7) * 4;           // k-row, chunk group
    const float* Bg = B + (long)bk * Nld + bn + bc4 * 4;

    float acc[4][8][4];
    #pragma unroll
    for (int i = 0; i < 4; i++)
        #pragma unroll
        for (int j = 0; j < 8; j++)
            #pragma unroll
            for (int q = 0; q < 4; q++) acc[i][j][q] = 0.f;

    auto issue = [&](int s) {
        const int st = s & (NSTAGE - 1);
        const uint32_t ab = sbase + st * A_STB;
        const float* ag = Ag + s * KT;
        #pragma unroll
        for (int c = 0; c < 4; c++)
            CP16(ab + tid * 64 + (((uint32_t)c ^ a_sw) << 4), ag + c * 4);
        const uint32_t bb = sbase + B_BASE + st * B_STB + bk * 544 + bc4 * 16;
        const float* bg = Bg + (long)s * KT * Nld;
        #pragma unroll
        for (int j = 0; j < 4; j++)
            CP16(bb + j * 16, bg + j * 4);
    };

    issue(0); CP_COMMIT();
    issue(1); CP_COMMIT();
    issue(2); CP_COMMIT();

    const int NIT = CDIM / KT;   // 32
    for (int s = 0; s < NIT; s++) {
        asm volatile("cp.async.wait_group 2;" ::: "memory");
        __syncthreads();
        if (s + 3 < NIT) issue(s + 3);
        CP_COMMIT();

        const int st = s & (NSTAGE - 1);
        const uint32_t ab = sbase + st * A_STB;
        const uint32_t bb = sbase + B_BASE + st * B_STB;
        #pragma unroll
        for (int ks = 0; ks < 2; ks++) {
            uint32_t af[4][4];
            #pragma unroll
            for (int mt = 0; mt < 4; mt++) {
                const int ml = wm + mt * 16 + row16;
                const uint32_t ad = ab + ml * 64 +
                    ((uint32_t)((ks * 2 + csel) ^ ((ml >> 1) & 3)) << 4);
                asm volatile("ldmatrix.sync.aligned.m8n8.x4.shared.b16 {%0,%1,%2,%3}, [%4];"
                    : "=r"(af[mt][0]), "=r"(af[mt][1]), "=r"(af[mt][2]), "=r"(af[mt][3])
                    : "r"(ad));
            }
            uint32_t bf[8][2];
            #pragma unroll
            for (int nt = 0; nt < 8; nt++) {
                const uint32_t b0 = bb + (ks * 8 + tg) * 544 + (wn + nt * 8 + g) * 4;
                asm volatile("ld.shared.b32 %0, [%1];" : "=r"(bf[nt][0]) : "r"(b0));
                asm volatile("ld.shared.b32 %0, [%1];" : "=r"(bf[nt][1]) : "r"(b0 + 4 * 544));
            }
            #pragma unroll
            for (int mt = 0; mt < 4; mt++)
                #pragma unroll
                for (int nt = 0; nt < 8; nt++)
                    mma_tf32(acc[mt][nt], af[mt], bf[nt]);
        }
    }

    // Epilogue
    #pragma unroll
    for (int mt = 0; mt < 4; mt++) {
        #pragma unroll
        for (int nt = 0; nt < 8; nt++) {
            const long r0 = bm + wm + mt * 16 + g;
            const int  cc = bn + wn + nt * 8 + 2 * tg;
            *(float2*)(C + r0 * Nld + cc)       = make_float2(acc[mt][nt][0], acc[mt][nt][1]);
            *(float2*)(C + (r0 + 8) * Nld + cc) = make_float2(acc[mt][nt][2], acc[mt][nt][3]);
        }
    }
}

// ---------------------------------------------------------------------------
// tf32 pre-round pass (float4)
// ---------------------------------------------------------------------------
__global__ void round_k(const float4* __restrict__ in, float4* __restrict__ o, long n4)
{
    long i = (long)blockIdx.x * blockDim.x + threadIdx.x;
    const long stride = (long)gridDim.x * blockDim.x;
    for (; i < n4; i += stride) {
        float4 v = in[i];
        o[i] = make_float4(__uint_as_float(f2tf32(v.x)), __uint_as_float(f2tf32(v.y)),
                           __uint_as_float(f2tf32(v.z)), __uint_as_float(f2tf32(v.w)));
    }
}

// ---------------------------------------------------------------------------
// Attention middle: one CTA per (n,t), softmax over HEADS axis.
// Output written tf32-rounded (feeds proj GEMM directly).
// ---------------------------------------------------------------------------
__global__ __launch_bounds__(256, 1)
void attn_kernel(const float* __restrict__ qkv, float* __restrict__ att)
{
    extern __shared__ float smem[];
    float* qs = smem;
    float* as = smem + QROWS * VV;

    const int b  = blockIdx.x;
    const int n  = b >> 8;
    const int ti = b & 255;
    const float* src = qkv + (long)n * QROWS * MCOL + ti * VV;
    const int tid = threadIdx.x;

    for (int idx = tid; idx < QROWS * VV; idx += 256) {
        int row = idx / VV;
        int j   = idx - row * VV;
        qs[idx] = src[(long)row * MCOL + j];
    }
    __syncthreads();

    const int h = tid >> 5;
    const int i = tid & 31;

    if (i < VV) {
        float q[HD];
        #pragma unroll
        for (int d = 0; d < HD; d++) q[d] = qs[(h * HD + d) * VV + i];
        const float* kb = qs + (CDIM + h * HD) * VV;
        for (int j = 0; j < VV; j++) {
            float acc = 0.f;
            #pragma unroll
            for (int d = 0; d < HD; d++) acc += q[d] * kb[d * VV + j];
            as[h * 625 + i * VV + j] = acc * 0.125f;
        }
    }
    __syncthreads();

    for (int p = tid; p < 625; p += 256) {
        float v[HEADS];
        #pragma unroll
        for (int hh = 0; hh < HEADS; hh++) v[hh] = as[hh * 625 + p];
        float m = v[0];
        #pragma unroll
        for (int hh = 1; hh < HEADS; hh++) m = fmaxf(m, v[hh]);
        float ssum = 0.f;
        #pragma unroll
        for (int hh = 0; hh < HEADS; hh++) { v[hh] = expf(v[hh] - m); ssum += v[hh]; }
        float inv = 1.f / ssum;
        #pragma unroll
        for (int hh = 0; hh < HEADS; hh++) as[hh * 625 + p] = v[hh] * inv;
    }
    __syncthreads();

    if (i < VV) {
        float o[HD];
        #pragma unroll
        for (int d = 0; d < HD; d++) o[d] = 0.f;
        const float* vb = qs + (2 * CDIM + h * HD) * VV;
        const float* ar = as + h * 625 + i * VV;
        for (int j = 0; j < VV; j++) {
            float a = ar[j];
            #pragma unroll
            for (int d = 0; d < HD; d++) o[d] += a * vb[d * VV + j];
        }
        float* dst = att + (long)n * CDIM * MCOL + (long)(h * HD) * MCOL + ti * VV + i;
        #pragma unroll
        for (int d = 0; d < HD; d++)
            dst[(long)d * MCOL] = __uint_as_float(f2tf32(o[d]));   // pre-round for proj GEMM
    }
}

// ---------------------------------------------------------------------------
extern "C" void kernel_launch(void* const* d_in, const int* in_sizes, int n_in,
                              void* d_out, int out_size)
{
    const float* x     = (const float*)d_in[0];   // [16,512,256,25]
    const float* wqkv  = (const float*)d_in[1];   // [1536,512]
    const float* wproj = (const float*)d_in[2];   // [512,512]
    float* out = (float*)d_out;

    float *qkv, *att, *xr, *wq, *wp;
    cudaGetSymbolAddress((void**)&qkv, g_qkv);
    cudaGetSymbolAddress((void**)&att, g_att);
    cudaGetSymbolAddress((void**)&xr,  g_xr);
    cudaGetSymbolAddress((void**)&wq,  g_wq);
    cudaGetSymbolAddress((void**)&wp,  g_wp);

    cudaFuncSetAttribute((const void*)tf32_gemm,
                         cudaFuncAttributeMaxDynamicSharedMemorySize, SMEM_G);
    const int attn_smem = (QROWS * VV + HEADS * 625) * (int)sizeof(float);
    cudaFuncSetAttribute((const void*)attn_kernel,
                         cudaFuncAttributeMaxDynamicSharedMemorySize, attn_smem);

    // tf32 pre-round passes
    round_k<<<4096, 256>>>((const float4*)x,     (float4*)xr, (long)NB * CDIM * MCOL / 4);
    round_k<<<512,  256>>>((const float4*)wqkv,  (float4*)wq, (long)QROWS * CDIM / 4);
    round_k<<<512,  256>>>((const float4*)wproj, (float4*)wp, (long)CDIM * CDIM / 4);

    // QKV: per-n [1536,6400] = W_qkv[1536,512] @ X_n[512,6400]
    tf32_gemm<<<dim3(MCOL / 128, QROWS / 128, NB), 128, SMEM_G>>>(
        wq, xr, qkv, MCOL, (long)CDIM * MCOL, (long)QROWS * MCOL);

    attn_kernel<<<dim3(NB * TDIM), 256, attn_smem>>>(qkv, att);

    // Proj: per-n [512,6400] = W_proj[512,512] @ O_n[512,6400]
    tf32_gemm<<<dim3(MCOL / 128, CDIM / 128, NB), 128, SMEM_G>>>(
        wp, att, out, MCOL, (long)CDIM * MCOL, (long)CDIM * MCOL);
}

// round 9
// speedup vs baseline: 3.2062x; 1.0404x over previous
#include <cuda_runtime.h>
#include <cuda_fp16.h>
#include <cstdint>
#include <math.h>

// Problem constants
#define NB    16
#define CDIM  512
#define TDIM  256
#define VV    25
#define HEADS 8
#define HD    64
#define MCOL  6400
#define QROWS 1536

// Scratch (__device__ globals per allocation-free rule)
__device__ float  g_qkv[(size_t)NB * QROWS * MCOL];   // QKV output (fp32)
__device__ __half g_att[(size_t)NB * CDIM * MCOL];    // attn output (fp16)
__device__ __half g_x16[(size_t)NB * CDIM * MCOL];    // x -> fp16
__device__ __half g_wq16[QROWS * CDIM];               // w_qkv -> fp16
__device__ __half g_wp16[CDIM * CDIM];                // w_proj -> fp16

// ---------------------------------------------------------------------------
__device__ __forceinline__ uint32_t smem_u32(const void* p) {
    uint32_t a;
    asm("{ .reg .u64 t; cvta.to.shared.u64 t, %1; cvt.u32.u64 %0, t; }" : "=r"(a) : "l"(p));
    return a;
}
__device__ __forceinline__ void mma_f16(float* c, const uint32_t* a, const uint32_t* b) {
    asm volatile(
        "mma.sync.aligned.m16n8k16.row.col.f32.f16.f16.f32 "
        "{%0,%1,%2,%3}, {%4,%5,%6,%7}, {%8,%9}, {%0,%1,%2,%3};"
        : "+f"(c[0]), "+f"(c[1]), "+f"(c[2]), "+f"(c[3])
        : "r"(a[0]), "r"(a[1]), "r"(a[2]), "r"(a[3]), "r"(b[0]), "r"(b[1]));
}
#define CP16(dst, src) \
    asm volatile("cp.async.cg.shared.global [%0], [%1], 16;" :: "r"(dst), "l"(src))
#define CP_COMMIT() asm volatile("cp.async.commit_group;" ::: "memory")

// ---------------------------------------------------------------------------
// fp16 tensor-core GEMM: C_f32[M,N] = A_f16[M,512] @ B_f16[512,N], row-major.
// CTA 128x256, 256 threads, 8 warps (2m x 4n) of 64x64. KT=32, 4-stage cp.async.
// A smem: [m][64B] rows (conflict-free unswizzled: bank16 = 4m+chunk).
// B smem: [k][528B] rows (264 halves, 16B pad): bank16 = (33k+n) mod 32.
// A frags: ldmatrix.x4.b16; B frags: ldmatrix.x2.trans.b16.
// ---------------------------------------------------------------------------
#define BMT 128
#define BNT 256
#define KT  32
#define NSTAGE 4
#define A_STB  (128 * 64)             // 8192
#define BROW   528
#define B_STB  (32 * BROW)            // 16896
#define B_OFF  (NSTAGE * A_STB)       // 32768
#define SMEM_G (B_OFF + NSTAGE * B_STB)  // 100352

__global__ __launch_bounds__(256, 1)
void h16_gemm(const __half* __restrict__ A, const __half* __restrict__ B,
              float* __restrict__ C, int Nld, long sB, long sC)
{
    extern __shared__ char sm[];
    const uint32_t sbase = smem_u32(sm);
    B += (long)blockIdx.z * sB;
    C += (long)blockIdx.z * sC;
    const int bm = blockIdx.y * BMT;
    const int bn = blockIdx.x * BNT;

    const int tid  = threadIdx.x;
    const int wid  = tid >> 5, lane = tid & 31;
    const int g    = lane >> 2, tg = lane & 3;
    const int wm   = (wid & 1) * 64, wn = (wid >> 1) * 64;

    // A staging: thread -> row m = tid>>1, chunks (tid&1)*2 + {0,1}
    const int am = tid >> 1, ac = (tid & 1) * 2;
    const __half* Ag = A + (long)(bm + am) * CDIM + ac * 8;
    const uint32_t a_soff = (uint32_t)(am * 64 + ac * 16);
    // B staging: thread -> k = tid>>3, chunks (tid&7) + j*8
    const int bk = tid >> 3, bc = tid & 7;
    const __half* Bg = B + (long)bk * Nld + bn + bc * 8;
    const uint32_t b_soff = (uint32_t)(bk * BROW + bc * 16);

    // ldmatrix lane addressing
    const int arow = lane & 15;          // row within 16-row tile
    const int achk = lane >> 4;          // 0/1 -> k-chunk within k16
    const int bkrow = (lane & 7) + ((lane >> 3) & 1) * 8;   // k row within k16

    float acc[4][8][4];
    #pragma unroll
    for (int i = 0; i < 4; i++)
        #pragma unroll
        for (int j = 0; j < 8; j++)
            #pragma unroll
            for (int q = 0; q < 4; q++) acc[i][j][q] = 0.f;

    auto issue = [&](int s) {
        const int st = s & (NSTAGE - 1);
        const uint32_t ab = sbase + st * A_STB + a_soff;
        const __half* ag = Ag + s * KT;
        #pragma unroll
        for (int j = 0; j < 2; j++)
            CP16(ab + j * 16, ag + j * 8);
        const uint32_t bb = sbase + B_OFF + st * B_STB + b_soff;
        const __half* bg = Bg + (long)s * KT * Nld;
        #pragma unroll
        for (int j = 0; j < 4; j++)
            CP16(bb + j * 128, bg + j * 64);
    };

    issue(0); CP_COMMIT();
    issue(1); CP_COMMIT();
    issue(2); CP_COMMIT();

    const int NIT = CDIM / KT;   // 16
    for (int s = 0; s < NIT; s++) {
        asm volatile("cp.async.wait_group 2;" ::: "memory");
        __syncthreads();
        if (s + 3 < NIT) issue(s + 3);
        CP_COMMIT();

        const int st = s & (NSTAGE - 1);
        const uint32_t ab = sbase + st * A_STB;
        const uint32_t bb = sbase + B_OFF + st * B_STB;
        #pragma unroll
        for (int ks = 0; ks < 2; ks++) {
            uint32_t af[4][4];
            #pragma unroll
            for (int mt = 0; mt < 4; mt++) {
                const int ml = wm + mt * 16 + arow;
                const uint32_t ad = ab + ml * 64 + (ks * 2 + achk) * 16;
                asm volatile("ldmatrix.sync.aligned.m8n8.x4.shared.b16 {%0,%1,%2,%3}, [%4];"
                    : "=r"(af[mt][0]), "=r"(af[mt][1]), "=r"(af[mt][2]), "=r"(af[mt][3])
                    : "r"(ad));
            }
            uint32_t bf[8][2];
            #pragma unroll
            for (int nt = 0; nt < 8; nt++) {
                const uint32_t bd = bb + (ks * 16 + bkrow) * BROW + (wn + nt * 8) * 2;
                asm volatile("ldmatrix.sync.aligned.m8n8.x2.trans.shared.b16 {%0,%1}, [%2];"
                    : "=r"(bf[nt][0]), "=r"(bf[nt][1]) : "r"(bd));
            }
            #pragma unroll
            for (int mt = 0; mt < 4; mt++)
                #pragma unroll
                for (int nt = 0; nt < 8; nt++)
                    mma_f16(acc[mt][nt], af[mt], bf[nt]);
        }
    }

    // Epilogue (m16n8 D layout: c0,c1 -> row g, c2,c3 -> row g+8; cols 2tg,2tg+1)
    #pragma unroll
    for (int mt = 0; mt < 4; mt++) {
        #pragma unroll
        for (int nt = 0; nt < 8; nt++) {
            const long r0 = bm + wm + mt * 16 + g;
            const int  cc = bn + wn + nt * 8 + 2 * tg;
            *(float2*)(C + r0 * Nld + cc)       = make_float2(acc[mt][nt][0], acc[mt][nt][1]);
            *(float2*)(C + (r0 + 8) * Nld + cc) = make_float2(acc[mt][nt][2], acc[mt][nt][3]);
        }
    }
}

// ---------------------------------------------------------------------------
// fp32 -> fp16 convert pass
// ---------------------------------------------------------------------------
__global__ void tohalf_k(const float4* __restrict__ in, __half2* __restrict__ o, long n4)
{
    long i = (long)blockIdx.x * blockDim.x + threadIdx.x;
    const long stride = (long)gridDim.x * blockDim.x;
    for (; i < n4; i += stride) {
        float4 v = in[i];
        o[2 * i]     = __floats2half2_rn(v.x, v.y);
        o[2 * i + 1] = __floats2half2_rn(v.z, v.w);
    }
}

// ---------------------------------------------------------------------------
// Attention middle: one CTA per (n,t), softmax over HEADS axis.
// Reads fp32 qkv, writes fp16 att (input rounding for proj GEMM).
// ---------------------------------------------------------------------------
__global__ __launch_bounds__(256, 1)
void attn_kernel(const float* __restrict__ qkv, __half* __restrict__ att)
{
    extern __shared__ float smem[];
    float* qs = smem;
    float* as = smem + QROWS * VV;

    const int b  = blockIdx.x;
    const int n  = b >> 8;
    const int ti = b & 255;
    const float* src = qkv + (long)n * QROWS * MCOL + ti * VV;
    const int tid = threadIdx.x;

    for (int idx = tid; idx < QROWS * VV; idx += 256) {
        int row = idx / VV;
        int j   = idx - row * VV;
        qs[idx] = src[(long)row * MCOL + j];
    }
    __syncthreads();

    const int h = tid >> 5;
    const int i = tid & 31;

    if (i < VV) {
        float q[HD];
        #pragma unroll
        for (int d = 0; d < HD; d++) q[d] = qs[(h * HD + d) * VV + i];
        const float* kb = qs + (CDIM + h * HD) * VV;
        for (int j = 0; j < VV; j++) {
            float acc = 0.f;
            #pragma unroll
            for (int d = 0; d < HD; d++) acc += q[d] * kb[d * VV + j];
            as[h * 625 + i * VV + j] = acc * 0.125f;
        }
    }
    __syncthreads();

    for (int p = tid; p < 625; p += 256) {
        float v[HEADS];
        #pragma unroll
        for (int hh = 0; hh < HEADS; hh++) v[hh] = as[hh * 625 + p];
        float m = v[0];
        #pragma unroll
        for (int hh = 1; hh < HEADS; hh++) m = fmaxf(m, v[hh]);
        float ssum = 0.f;
        #pragma unroll
        for (int hh = 0; hh < HEADS; hh++) { v[hh] = expf(v[hh] - m); ssum += v[hh]; }
        float inv = 1.f / ssum;
        #pragma unroll
        for (int hh = 0; hh < HEADS; hh++) as[hh * 625 + p] = v[hh] * inv;
    }
    __syncthreads();

    if (i < VV) {
        float o[HD];
        #pragma unroll
        for (int d = 0; d < HD; d++) o[d] = 0.f;
        const float* vb = qs + (2 * CDIM + h * HD) * VV;
        const float* ar = as + h * 625 + i * VV;
        for (int j = 0; j < VV; j++) {
            float a = ar[j];
            #pragma unroll
            for (int d = 0; d < HD; d++) o[d] += a * vb[d * VV + j];
        }
        __half* dst = att + (long)n * CDIM * MCOL + (long)(h * HD) * MCOL + ti * VV + i;
        #pragma unroll
        for (int d = 0; d < HD; d++)
            dst[(long)d * MCOL] = __float2half_rn(o[d]);
    }
}

// ---------------------------------------------------------------------------
extern "C" void kernel_launch(void* const* d_in, const int* in_sizes, int n_in,
                              void* d_out, int out_size)
{
    const float* x     = (const float*)d_in[0];   // [16,512,256,25]
    const float* wqkv  = (const float*)d_in[1];   // [1536,512]
    const float* wproj = (const float*)d_in[2];   // [512,512]
    float* out = (float*)d_out;

    float  *qkv;
    __half *att, *x16, *wq16, *wp16;
    cudaGetSymbolAddress((void**)&qkv,  g_qkv);
    cudaGetSymbolAddress((void**)&att,  g_att);
    cudaGetSymbolAddress((void**)&x16,  g_x16);
    cudaGetSymbolAddress((void**)&wq16, g_wq16);
    cudaGetSymbolAddress((void**)&wp16, g_wp16);

    cudaFuncSetAttribute((const void*)h16_gemm,
                         cudaFuncAttributeMaxDynamicSharedMemorySize, SMEM_G);
    const int attn_smem = (QROWS * VV + HEADS * 625) * (int)sizeof(float);
    cudaFuncSetAttribute((const void*)attn_kernel,
                         cudaFuncAttributeMaxDynamicSharedMemorySize, attn_smem);

    // fp16 convert passes
    tohalf_k<<<4096, 256>>>((const float4*)x,     (__half2*)x16,  (long)NB * CDIM * MCOL / 4);
    tohalf_k<<<512,  256>>>((const float4*)wqkv,  (__half2*)wq16, (long)QROWS * CDIM / 4);
    tohalf_k<<<512,  256>>>((const float4*)wproj, (__half2*)wp16, (long)CDIM * CDIM / 4);

    // QKV: per-n [1536,6400] = W_qkv[1536,512] @ X_n[512,6400]
    h16_gemm<<<dim3(MCOL / BNT, QROWS / BMT, NB), 256, SMEM_G>>>(
        wq16, x16, qkv, MCOL, (long)CDIM * MCOL, (long)QROWS * MCOL);

    attn_kernel<<<dim3(NB * TDIM), 256, attn_smem>>>(qkv, att);

    // Proj: per-n [512,6400] = W_proj[512,512] @ O_n[512,6400]
    h16_gemm<<<dim3(MCOL / BNT, CDIM / BMT, NB), 256, SMEM_G>>>(
        wp16, att, out, MCOL, (long)CDIM * MCOL, (long)CDIM * MCOL);
}

// round 12
// speedup vs baseline: 6.6603x; 2.0773x over previous
#include <cuda_runtime.h>
#include <cuda_fp16.h>
#include <cstdint>
#include <math.h>

// Problem constants
#define NB    16
#define CDIM  512
#define TDIM  256
#define VV    25
#define HEADS 8
#define HD    64
#define MCOL  6400
#define QROWS 1536

// Scratch (__device__ globals per allocation-free rule)
__device__ float  g_qkv[(size_t)NB * QROWS * MCOL];   // QKV output (fp32)
__device__ __half g_att[(size_t)NB * CDIM * MCOL];    // attn output (fp16)
__device__ __half g_x16[(size_t)NB * CDIM * MCOL];    // x -> fp16
__device__ __half g_wq16[QROWS * CDIM];               // w_qkv -> fp16
__device__ __half g_wp16[CDIM * CDIM];                // w_proj -> fp16

// ---------------------------------------------------------------------------
__device__ __forceinline__ uint32_t smem_u32(const void* p) {
    uint32_t a;
    asm("{ .reg .u64 t; cvta.to.shared.u64 t, %1; cvt.u32.u64 %0, t; }" : "=r"(a) : "l"(p));
    return a;
}
__device__ __forceinline__ void mma_f16(float* c, const uint32_t* a, const uint32_t* b) {
    asm volatile(
        "mma.sync.aligned.m16n8k16.row.col.f32.f16.f16.f32 "
        "{%0,%1,%2,%3}, {%4,%5,%6,%7}, {%8,%9}, {%0,%1,%2,%3};"
        : "+f"(c[0]), "+f"(c[1]), "+f"(c[2]), "+f"(c[3])
        : "r"(a[0]), "r"(a[1]), "r"(a[2]), "r"(a[3]), "r"(b[0]), "r"(b[1]));
}
#define CP16(dst, src) \
    asm volatile("cp.async.cg.shared.global [%0], [%1], 16;" :: "r"(dst), "l"(src))
#define CP_COMMIT() asm volatile("cp.async.commit_group;" ::: "memory")

// ---------------------------------------------------------------------------
// fp16 GEMM: C_f32[M,N] = A_f16[M,512] @ B_f16[512,N], row-major.
// CTA 128x128, 8 warps (2m x 4n) of 64x32, KT=32, 4-stage cp.async,
// 2 CTAs/SM for latency overlap.
// A smem: [m][64B] rows, chunk-xor swizzle (c ^= (m>>1)&3): ldmatrix phase rows
//   {0,2,4,6} and {1,3,5,7} each span xors 0..3 -> all 8 rows distinct 16B banks.
// B smem: [k][272B] rows (128 halves + 16B pad): addr16 = 17k+c -> conflict-free.
// ---------------------------------------------------------------------------
#define BMT 128
#define BNT 128
#define KT  32
#define NSTAGE 4
#define A_STB  (128 * 64)               // 8192
#define BROW   272
#define B_STB  (32 * BROW)              // 8704
#define B_OFF  (NSTAGE * A_STB)         // 32768
#define SMEM_G (B_OFF + NSTAGE * B_STB) // 67584

__global__ __launch_bounds__(256, 2)
void h16_gemm(const __half* __restrict__ A, const __half* __restrict__ B,
              float* __restrict__ C, int Nld, long sB, long sC)
{
    extern __shared__ char sm[];
    const uint32_t sbase = smem_u32(sm);
    B += (long)blockIdx.z * sB;
    C += (long)blockIdx.z * sC;
    const int bm = blockIdx.y * BMT;
    const int bn = blockIdx.x * BNT;

    const int tid  = threadIdx.x;
    const int wid  = tid >> 5, lane = tid & 31;
    const int g    = lane >> 2, tg = lane & 3;
    const int wm   = (wid & 1) * 64, wn = (wid >> 1) * 32;

    // A staging: thread -> row am = tid>>1, chunk16 pair {2ac, 2ac+1}
    const int am = tid >> 1, ac = tid & 1;
    const __half* Ag = A + (long)(bm + am) * CDIM + ac * 16;
    const uint32_t am_sw = (uint32_t)((am >> 1) & 3);
    // B staging: thread -> k row bk = tid>>3, chunks bc, bc+8
    const int bk = tid >> 3, bc = tid & 7;
    const __half* Bg = B + (long)bk * Nld + bn + bc * 8;
    const uint32_t b_soff = (uint32_t)(bk * BROW + bc * 16);

    // ldmatrix lane selectors
    const int arow = lane & 15;                              // m row in 16-tile
    const int achk = lane >> 4;                              // k-chunk in k16
    const int bkrow = (lane & 7) + ((lane >> 3) & 1) * 8;    // k row in k16

    float acc[4][4][4];
    #pragma unroll
    for (int i = 0; i < 4; i++)
        #pragma unroll
        for (int j = 0; j < 4; j++)
            #pragma unroll
            for (int q = 0; q < 4; q++) acc[i][j][q] = 0.f;

    auto issue = [&](int s) {
        const int st = s & (NSTAGE - 1);
        const uint32_t ab = sbase + st * A_STB + am * 64;
        const __half* ag = Ag + s * KT;
        #pragma unroll
        for (int j = 0; j < 2; j++)
            CP16(ab + (((uint32_t)(2 * ac + j)) ^ am_sw) * 16, ag + j * 8);
        const uint32_t bb = sbase + B_OFF + st * B_STB + b_soff;
        const __half* bg = Bg + (long)s * KT * Nld;
        CP16(bb, bg);
        CP16(bb + 128, bg + 64);
    };

    issue(0); CP_COMMIT();
    issue(1); CP_COMMIT();
    issue(2); CP_COMMIT();

    const int NIT = CDIM / KT;   // 16
    for (int s = 0; s < NIT; s++) {
        asm volatile("cp.async.wait_group 2;" ::: "memory");
        __syncthreads();
        if (s + 3 < NIT) issue(s + 3);
        CP_COMMIT();

        const int st = s & (NSTAGE - 1);
        const uint32_t ab = sbase + st * A_STB;
        const uint32_t bb = sbase + B_OFF + st * B_STB;
        #pragma unroll
        for (int ks = 0; ks < 2; ks++) {
            uint32_t af[4][4];
            #pragma unroll
            for (int mt = 0; mt < 4; mt++) {
                const int ml = wm + mt * 16 + arow;
                const uint32_t ad = ab + ml * 64 +
                    (((uint32_t)(ks * 2 + achk)) ^ ((uint32_t)((ml >> 1) & 3))) * 16;
                asm volatile("ldmatrix.sync.aligned.m8n8.x4.shared.b16 {%0,%1,%2,%3}, [%4];"
                    : "=r"(af[mt][0]), "=r"(af[mt][1]), "=r"(af[mt][2]), "=r"(af[mt][3])
                    : "r"(ad));
            }
            uint32_t bf[4][2];
            #pragma unroll
            for (int nt = 0; nt < 4; nt++) {
                const uint32_t bd = bb + (ks * 16 + bkrow) * BROW + (wn + nt * 8) * 2;
                asm volatile("ldmatrix.sync.aligned.m8n8.x2.trans.shared.b16 {%0,%1}, [%2];"
                    : "=r"(bf[nt][0]), "=r"(bf[nt][1]) : "r"(bd));
            }
            #pragma unroll
            for (int mt = 0; mt < 4; mt++)
                #pragma unroll
                for (int nt = 0; nt < 4; nt++)
                    mma_f16(acc[mt][nt], af[mt], bf[nt]);
        }
    }

    // Epilogue
    #pragma unroll
    for (int mt = 0; mt < 4; mt++) {
        #pragma unroll
        for (int nt = 0; nt < 4; nt++) {
            const long r0 = bm + wm + mt * 16 + g;
            const int  cc = bn + wn + nt * 8 + 2 * tg;
            *(float2*)(C + r0 * Nld + cc)       = make_float2(acc[mt][nt][0], acc[mt][nt][1]);
            *(float2*)(C + (r0 + 8) * Nld + cc) = make_float2(acc[mt][nt][2], acc[mt][nt][3]);
        }
    }
}

// ---------------------------------------------------------------------------
// fp32 -> fp16 convert pass
// ---------------------------------------------------------------------------
__global__ void tohalf_k(const float4* __restrict__ in, __half2* __restrict__ o, long n4)
{
    long i = (long)blockIdx.x * blockDim.x + threadIdx.x;
    const long stride = (long)gridDim.x * blockDim.x;
    for (; i < n4; i += stride) {
        float4 v = in[i];
        o[2 * i]     = __floats2half2_rn(v.x, v.y);
        o[2 * i + 1] = __floats2half2_rn(v.z, v.w);
    }
}

// ---------------------------------------------------------------------------
// Attention middle: one CTA per (n,t), softmax over HEADS axis.
// smem floats: QV shared region [0,12800) | K [12800,25600) | fp16 probs after
// => 112.6 KB -> 2 CTAs/SM.
// ---------------------------------------------------------------------------
#define AS_OFF  (512 * VV)            // 12800: K starts here
#define PR_OFF  (2 * 512 * VV)        // 25600: fp16 probs start (float index)
#define ATTN_SMEM (PR_OFF * 4 + HEADS * 625 * 2 + 240)

__global__ __launch_bounds__(256, 2)
void attn_kernel(const float* __restrict__ qkv, __half* __restrict__ att)
{
    extern __shared__ float smem[];
    float*  qv  = smem;                       // Q, later V: [512][25]
    float*  ks  = smem + AS_OFF;              // K: [512][25]
    __half* pr  = (__half*)(smem + PR_OFF);   // logits/probs [8][625]

    const int b  = blockIdx.x;
    const int n  = b >> 8;
    const int ti = b & 255;
    const float* src = qkv + (long)n * QROWS * MCOL + ti * VV;
    const int tid = threadIdx.x;

    // Stage Q (rows 0-511) and K (rows 512-1023): warp -> row, lanes 0-24
    {
        const float* srcK = src + (long)512 * MCOL;
        for (int idx = tid; idx < 512 * 32; idx += 256) {
            const int r = idx >> 5, l = idx & 31;
            if (l < VV) {
                qv[r * VV + l] = src [(long)r * MCOL + l];
                ks[r * VV + l] = srcK[(long)r * MCOL + l];
            }
        }
    }
    __syncthreads();

    const int h = tid >> 5;
    const int i = tid & 31;

    // Phase 1: logits[h][i][j] = 0.125 * q_i . k_j  (fp16 store)
    if (i < VV) {
        float q[HD];
        #pragma unroll
        for (int d = 0; d < HD; d++) q[d] = qv[(h * HD + d) * VV + i];
        const float* kb = ks + (h * HD) * VV;
        for (int j = 0; j < VV; j++) {
            float acc = 0.f;
            #pragma unroll
            for (int d = 0; d < HD; d++) acc += q[d] * kb[d * VV + j];
            pr[h * 625 + i * VV + j] = __float2half_rn(acc * 0.125f);
        }
    }
    __syncthreads();

    // Phase 2: softmax over heads; then overwrite Q region with V
    for (int p = tid; p < 625; p += 256) {
        float v[HEADS];
        #pragma unroll
        for (int hh = 0; hh < HEADS; hh++) v[hh] = __half2float(pr[hh * 625 + p]);
        float m = v[0];
        #pragma unroll
        for (int hh = 1; hh < HEADS; hh++) m = fmaxf(m, v[hh]);
        float ssum = 0.f;
        #pragma unroll
        for (int hh = 0; hh < HEADS; hh++) { v[hh] = expf(v[hh] - m); ssum += v[hh]; }
        float inv = 1.f / ssum;
        #pragma unroll
        for (int hh = 0; hh < HEADS; hh++) pr[hh * 625 + p] = __float2half_rn(v[hh] * inv);
    }
    {
        const float* srcV = src + (long)1024 * MCOL;
        for (int idx = tid; idx < 512 * 32; idx += 256) {
            const int r = idx >> 5, l = idx & 31;
            if (l < VV)
                qv[r * VV + l] = srcV[(long)r * MCOL + l];
        }
    }
    __syncthreads();

    // Phase 3: out[h][i][d] = sum_j probs[h][i][j] * v[h][j][d]
    if (i < VV) {
        float o[HD];
        #pragma unroll
        for (int d = 0; d < HD; d++) o[d] = 0.f;
        const float* vb = qv + (h * HD) * VV;
        const __half* ar = pr + h * 625 + i * VV;
        for (int j = 0; j < VV; j++) {
            const float a = __half2float(ar[j]);
            #pragma unroll
            for (int d = 0; d < HD; d++) o[d] += a * vb[d * VV + j];
        }
        __half* dst = att + (long)n * CDIM * MCOL + (long)(h * HD) * MCOL + ti * VV + i;
        #pragma unroll
        for (int d = 0; d < HD; d++)
            dst[(long)d * MCOL] = __float2half_rn(o[d]);
    }
}

// ---------------------------------------------------------------------------
extern "C" void kernel_launch(void* const* d_in, const int* in_sizes, int n_in,
                              void* d_out, int out_size)
{
    const float* x     = (const float*)d_in[0];   // [16,512,256,25]
    const float* wqkv  = (const float*)d_in[1];   // [1536,512]
    const float* wproj = (const float*)d_in[2];   // [512,512]
    float* out = (float*)d_out;

    float  *qkv;
    __half *att, *x16, *wq16, *wp16;
    cudaGetSymbolAddress((void**)&qkv,  g_qkv);
    cudaGetSymbolAddress((void**)&att,  g_att);
    cudaGetSymbolAddress((void**)&x16,  g_x16);
    cudaGetSymbolAddress((void**)&wq16, g_wq16);
    cudaGetSymbolAddress((void**)&wp16, g_wp16);

    cudaFuncSetAttribute((const void*)h16_gemm,
                         cudaFuncAttributeMaxDynamicSharedMemorySize, SMEM_G);
    cudaFuncSetAttribute((const void*)attn_kernel,
                         cudaFuncAttributeMaxDynamicSharedMemorySize, ATTN_SMEM);

    // fp16 convert passes
    tohalf_k<<<4096, 256>>>((const float4*)x,     (__half2*)x16,  (long)NB * CDIM * MCOL / 4);
    tohalf_k<<<512,  256>>>((const float4*)wqkv,  (__half2*)wq16, (long)QROWS * CDIM / 4);
    tohalf_k<<<512,  256>>>((const float4*)wproj, (__half2*)wp16, (long)CDIM * CDIM / 4);

    // QKV: per-n [1536,6400] = W_qkv[1536,512] @ X_n[512,6400]
    h16_gemm<<<dim3(MCOL / BNT, QROWS / BMT, NB), 256, SMEM_G>>>(
        wq16, x16, qkv, MCOL, (long)CDIM * MCOL, (long)QROWS * MCOL);

    attn_kernel<<<dim3(NB * TDIM), 256, ATTN_SMEM>>>(qkv, att);

    // Proj: per-n [512,6400] = W_proj[512,512] @ O_n[512,6400]
    h16_gemm<<<dim3(MCOL / BNT, CDIM / BMT, NB), 256, SMEM_G>>>(
        wp16, att, out, MCOL, (long)CDIM * MCOL, (long)CDIM * MCOL);
}

// round 13
// speedup vs baseline: 7.5290x; 1.1304x over previous
#include <cuda_runtime.h>
#include <cuda_fp16.h>
#include <cstdint>
#include <math.h>

// Problem constants
#define NB    16
#define CDIM  512
#define TDIM  256
#define VV    25
#define HEADS 8
#define HD    64
#define MCOL  6400
#define QROWS 1536

// Scratch (__device__ globals per allocation-free rule)
__device__ float  g_qkv[(size_t)NB * QROWS * MCOL];   // QKV output (fp32)
__device__ __half g_att[(size_t)NB * CDIM * MCOL];    // attn output (fp16)
__device__ __half g_x16[(size_t)NB * CDIM * MCOL];    // x -> fp16
__device__ __half g_wq16[QROWS * CDIM];               // w_qkv -> fp16
__device__ __half g_wp16[CDIM * CDIM];                // w_proj -> fp16

// ---------------------------------------------------------------------------
__device__ __forceinline__ uint32_t smem_u32(const void* p) {
    uint32_t a;
    asm("{ .reg .u64 t; cvta.to.shared.u64 t, %1; cvt.u32.u64 %0, t; }" : "=r"(a) : "l"(p));
    return a;
}
__device__ __forceinline__ void mma_f16(float* c, const uint32_t* a, const uint32_t* b) {
    asm volatile(
        "mma.sync.aligned.m16n8k16.row.col.f32.f16.f16.f32 "
        "{%0,%1,%2,%3}, {%4,%5,%6,%7}, {%8,%9}, {%0,%1,%2,%3};"
        : "+f"(c[0]), "+f"(c[1]), "+f"(c[2]), "+f"(c[3])
        : "r"(a[0]), "r"(a[1]), "r"(a[2]), "r"(a[3]), "r"(b[0]), "r"(b[1]));
}
#define CP16(dst, src) \
    asm volatile("cp.async.cg.shared.global [%0], [%1], 16;" :: "r"(dst), "l"(src))
#define CP_COMMIT() asm volatile("cp.async.commit_group;" ::: "memory")

// ---------------------------------------------------------------------------
// fp16 GEMM: C_f32[M,N] = A_f16[M,512] @ B_f16[512,N], row-major.
// CTA 128x128, 8 warps (2m x 4n) of 64x32, KT=32, 4-stage cp.async, 2 CTAs/SM.
// A smem: [m][64B] rows, chunk-xor swizzle (c ^= (m>>1)&3) -> conflict-free.
// B smem: [k][272B] rows: addr16 = 17k+c -> conflict-free (x4.trans verified:
//   cross-column collision needs dk==17 (17*17=1 mod 32) -> impossible).
// ---------------------------------------------------------------------------
#define BMT 128
#define BNT 128
#define KT  32
#define NSTAGE 4
#define A_STB  (128 * 64)               // 8192
#define BROW   272
#define B_STB  (32 * BROW)              // 8704
#define B_OFF  (NSTAGE * A_STB)         // 32768
#define SMEM_G (B_OFF + NSTAGE * B_STB) // 67584

__global__ __launch_bounds__(256, 2)
void h16_gemm(const __half* __restrict__ A, const __half* __restrict__ B,
              float* __restrict__ C, int Nld, long sB, long sC)
{
    extern __shared__ char sm[];
    const uint32_t sbase = smem_u32(sm);
    B += (long)blockIdx.z * sB;
    C += (long)blockIdx.z * sC;
    const int bm = blockIdx.y * BMT;
    const int bn = blockIdx.x * BNT;

    const int tid  = threadIdx.x;
    const int wid  = tid >> 5, lane = tid & 31;
    const int g    = lane >> 2, tg = lane & 3;
    const int wm   = (wid & 1) * 64, wn = (wid >> 1) * 32;

    // A staging: thread -> row am = tid>>1, chunk16 pair {2ac, 2ac+1}
    const int am = tid >> 1, ac = tid & 1;
    const __half* Ag = A + (long)(bm + am) * CDIM + ac * 16;
    const uint32_t am_sw = (uint32_t)((am >> 1) & 3);
    // B staging: thread -> k row bk = tid>>3, chunks bc, bc+8
    const int bk = tid >> 3, bc = tid & 7;
    const __half* Bg = B + (long)bk * Nld + bn + bc * 8;
    const uint32_t b_soff = (uint32_t)(bk * BROW + bc * 16);

    // ldmatrix lane selectors
    const int arow  = lane & 15;                             // m row in 16-tile
    const int achk  = lane >> 4;                             // k-chunk in k16
    const int bkrow = (lane & 7) + ((lane >> 3) & 1) * 8;    // k row in k16
    const int bcoff = ((lane >> 4) & 1) * 8;                 // col group for x4

    float acc[4][4][4];
    #pragma unroll
    for (int i = 0; i < 4; i++)
        #pragma unroll
        for (int j = 0; j < 4; j++)
            #pragma unroll
            for (int q = 0; q < 4; q++) acc[i][j][q] = 0.f;

    auto issue = [&](int s) {
        const int st = s & (NSTAGE - 1);
        const uint32_t ab = sbase + st * A_STB + am * 64;
        const __half* ag = Ag + s * KT;
        #pragma unroll
        for (int j = 0; j < 2; j++)
            CP16(ab + (((uint32_t)(2 * ac + j)) ^ am_sw) * 16, ag + j * 8);
        const uint32_t bb = sbase + B_OFF + st * B_STB + b_soff;
        const __half* bg = Bg + (long)s * KT * Nld;
        CP16(bb, bg);
        CP16(bb + 128, bg + 64);
    };

    issue(0); CP_COMMIT();
    issue(1); CP_COMMIT();
    issue(2); CP_COMMIT();

    const int NIT = CDIM / KT;   // 16
    for (int s = 0; s < NIT; s++) {
        asm volatile("cp.async.wait_group 2;" ::: "memory");
        __syncthreads();
        if (s + 3 < NIT) issue(s + 3);
        CP_COMMIT();

        const int st = s & (NSTAGE - 1);
        const uint32_t ab = sbase + st * A_STB;
        const uint32_t bb = sbase + B_OFF + st * B_STB;
        #pragma unroll
        for (int ks = 0; ks < 2; ks++) {
            uint32_t af[4][4];
            #pragma unroll
            for (int mt = 0; mt < 4; mt++) {
                const int ml = wm + mt * 16 + arow;
                const uint32_t ad = ab + ml * 64 +
                    (((uint32_t)(ks * 2 + achk)) ^ ((uint32_t)((ml >> 1) & 3))) * 16;
                asm volatile("ldmatrix.sync.aligned.m8n8.x4.shared.b16 {%0,%1,%2,%3}, [%4];"
                    : "=r"(af[mt][0]), "=r"(af[mt][1]), "=r"(af[mt][2]), "=r"(af[mt][3])
                    : "r"(ad));
            }
            uint32_t bf[4][2];
            #pragma unroll
            for (int ntp = 0; ntp < 2; ntp++) {
                const uint32_t bd = bb + (ks * 16 + bkrow) * BROW +
                                    (wn + ntp * 16 + bcoff) * 2;
                asm volatile("ldmatrix.sync.aligned.m8n8.x4.trans.shared.b16 {%0,%1,%2,%3}, [%4];"
                    : "=r"(bf[2 * ntp][0]), "=r"(bf[2 * ntp][1]),
                      "=r"(bf[2 * ntp + 1][0]), "=r"(bf[2 * ntp + 1][1])
                    : "r"(bd));
            }
            #pragma unroll
            for (int mt = 0; mt < 4; mt++)
                #pragma unroll
                for (int nt = 0; nt < 4; nt++)
                    mma_f16(acc[mt][nt], af[mt], bf[nt]);
        }
    }

    // Epilogue
    #pragma unroll
    for (int mt = 0; mt < 4; mt++) {
        #pragma unroll
        for (int nt = 0; nt < 4; nt++) {
            const long r0 = bm + wm + mt * 16 + g;
            const int  cc = bn + wn + nt * 8 + 2 * tg;
            *(float2*)(C + r0 * Nld + cc)       = make_float2(acc[mt][nt][0], acc[mt][nt][1]);
            *(float2*)(C + (r0 + 8) * Nld + cc) = make_float2(acc[mt][nt][2], acc[mt][nt][3]);
        }
    }
}

// ---------------------------------------------------------------------------
// fp32 -> fp16 convert pass
// ---------------------------------------------------------------------------
__global__ void tohalf_k(const float4* __restrict__ in, __half2* __restrict__ o, long n4)
{
    long i = (long)blockIdx.x * blockDim.x + threadIdx.x;
    const long stride = (long)gridDim.x * blockDim.x;
    for (; i < n4; i += stride) {
        float4 v = in[i];
        o[2 * i]     = __floats2half2_rn(v.x, v.y);
        o[2 * i + 1] = __floats2half2_rn(v.z, v.w);
    }
}

// ---------------------------------------------------------------------------
// Attention middle: one CTA per (n,t), softmax over HEADS axis.
// smem floats: QV [512][25] at 0 | K padded [512][26] at AS_OFF | fp16 probs.
// Total 114448 B -> 2 CTAs/SM.
// Phase 1: acc[25] regs, d outer (independent FMA chains), K rows as float2.
// ---------------------------------------------------------------------------
#define KPAD    26
#define AS_OFF  (512 * VV)                  // 12800: K starts here
#define PR_OFF  (AS_OFF + 512 * KPAD)       // 26112: fp16 probs start (float idx)
#define ATTN_SMEM (PR_OFF * 4 + HEADS * 625 * 2)   // 114448

__global__ __launch_bounds__(256, 2)
void attn_kernel(const float* __restrict__ qkv, __half* __restrict__ att)
{
    extern __shared__ float smem[];
    float*  qv  = smem;                       // Q, later V: [512][25]
    float*  ks  = smem + AS_OFF;              // K: [512][26] (col 25 = pad)
    __half* pr  = (__half*)(smem + PR_OFF);   // logits/probs [8][625]

    const int b  = blockIdx.x;
    const int n  = b >> 8;
    const int ti = b & 255;
    const float* src = qkv + (long)n * QROWS * MCOL + ti * VV;
    const int tid = threadIdx.x;

    // Stage Q (rows 0-511) and K (rows 512-1023): warp -> row, lanes 0-24
    {
        const float* srcK = src + (long)512 * MCOL;
        for (int idx = tid; idx < 512 * 32; idx += 256) {
            const int r = idx >> 5, l = idx & 31;
            if (l < VV) {
                qv[r * VV + l]   = src [(long)r * MCOL + l];
                ks[r * KPAD + l] = srcK[(long)r * MCOL + l];
            }
        }
    }
    __syncthreads();

    const int h = tid >> 5;
    const int i = tid & 31;

    // Phase 1: logits[h][i][j] = 0.125 * sum_d q[d][i]*k[d][j]
    if (i < VV) {
        const float* qcol = qv + (h * HD) * VV + i;   // stride VV per d
        const float* kb   = ks + (h * HD) * KPAD;
        float acc[VV];
        #pragma unroll
        for (int j = 0; j < VV; j++) acc[j] = 0.f;
        #pragma unroll 4
        for (int d = 0; d < HD; d++) {
            const float qd = qcol[d * VV];
            const float2* row = (const float2*)(kb + d * KPAD);
            #pragma unroll
            for (int jp = 0; jp < 12; jp++) {
                const float2 kv = row[jp];
                acc[2 * jp]     += qd * kv.x;
                acc[2 * jp + 1] += qd * kv.y;
            }
            acc[24] += qd * kb[d * KPAD + 24];
        }
        __half* prr = pr + h * 625 + i * VV;
        #pragma unroll
        for (int j = 0; j < VV; j++)
            prr[j] = __float2half_rn(acc[j] * 0.125f);
    }
    __syncthreads();

    // Phase 2: softmax over heads; then overwrite Q region with V
    for (int p = tid; p < 625; p += 256) {
        float v[HEADS];
        #pragma unroll
        for (int hh = 0; hh < HEADS; hh++) v[hh] = __half2float(pr[hh * 625 + p]);
        float m = v[0];
        #pragma unroll
        for (int hh = 1; hh < HEADS; hh++) m = fmaxf(m, v[hh]);
        float ssum = 0.f;
        #pragma unroll
        for (int hh = 0; hh < HEADS; hh++) { v[hh] = expf(v[hh] - m); ssum += v[hh]; }
        float inv = 1.f / ssum;
        #pragma unroll
        for (int hh = 0; hh < HEADS; hh++) pr[hh * 625 + p] = __float2half_rn(v[hh] * inv);
    }
    {
        const float* srcV = src + (long)1024 * MCOL;
        for (int idx = tid; idx < 512 * 32; idx += 256) {
            const int r = idx >> 5, l = idx & 31;
            if (l < VV)
                qv[r * VV + l] = srcV[(long)r * MCOL + l];
        }
    }
    __syncthreads();

    // Phase 3: out[h][i][d] = sum_j probs[h][i][j] * v[h][j][d]
    if (i < VV) {
        float o[HD];
        #pragma unroll
        for (int d = 0; d < HD; d++) o[d] = 0.f;
        const float* vb = qv + (h * HD) * VV;
        const __half* ar = pr + h * 625 + i * VV;
        for (int j = 0; j < VV; j++) {
            const float a = __half2float(ar[j]);
            #pragma unroll
            for (int d = 0; d < HD; d++) o[d] += a * vb[d * VV + j];
        }
        __half* dst = att + (long)n * CDIM * MCOL + (long)(h * HD) * MCOL + ti * VV + i;
        #pragma unroll
        for (int d = 0; d < HD; d++)
            dst[(long)d * MCOL] = __float2half_rn(o[d]);
    }
}

// ---------------------------------------------------------------------------
extern "C" void kernel_launch(void* const* d_in, const int* in_sizes, int n_in,
                              void* d_out, int out_size)
{
    const float* x     = (const float*)d_in[0];   // [16,512,256,25]
    const float* wqkv  = (const float*)d_in[1];   // [1536,512]
    const float* wproj = (const float*)d_in[2];   // [512,512]
    float* out = (float*)d_out;

    float  *qkv;
    __half *att, *x16, *wq16, *wp16;
    cudaGetSymbolAddress((void**)&qkv,  g_qkv);
    cudaGetSymbolAddress((void**)&att,  g_att);
    cudaGetSymbolAddress((void**)&x16,  g_x16);
    cudaGetSymbolAddress((void**)&wq16, g_wq16);
    cudaGetSymbolAddress((void**)&wp16, g_wp16);

    cudaFuncSetAttribute((const void*)h16_gemm,
                         cudaFuncAttributeMaxDynamicSharedMemorySize, SMEM_G);
    cudaFuncSetAttribute((const void*)attn_kernel,
                         cudaFuncAttributeMaxDynamicSharedMemorySize, ATTN_SMEM);

    // fp16 convert passes
    tohalf_k<<<4096, 256>>>((const float4*)x,     (__half2*)x16,  (long)NB * CDIM * MCOL / 4);
    tohalf_k<<<512,  256>>>((const float4*)wqkv,  (__half2*)wq16, (long)QROWS * CDIM / 4);
    tohalf_k<<<512,  256>>>((const float4*)wproj, (__half2*)wp16, (long)CDIM * CDIM / 4);

    // QKV: per-n [1536,6400] = W_qkv[1536,512] @ X_n[512,6400]
    h16_gemm<<<dim3(MCOL / BNT, QROWS / BMT, NB), 256, SMEM_G>>>(
        wq16, x16, qkv, MCOL, (long)CDIM * MCOL, (long)QROWS * MCOL);

    attn_kernel<<<dim3(NB * TDIM), 256, ATTN_SMEM>>>(qkv, att);

    // Proj: per-n [512,6400] = W_proj[512,512] @ O_n[512,6400]
    h16_gemm<<<dim3(MCOL / BNT, CDIM / BMT, NB), 256, SMEM_G>>>(
        wp16, att, out, MCOL, (long)CDIM * MCOL, (long)CDIM * MCOL);
}